// round 1
// baseline (speedup 1.0000x reference)
#include <cuda_runtime.h>
#include <math.h>

#define S_IMG 2048
#define S_TXT 256
#define SEQ   2304
#define DIM   3072
#define HEADS 24
#define HD    128

// ---------------- scratch (device globals: allocation-free) ----------------
__device__ float g_x[SEQ * DIM];
__device__ float g_q[SEQ * DIM];
__device__ float g_k[SEQ * DIM];
__device__ float g_v[SEQ * DIM];
__device__ float g_attn[SEQ * DIM];

// ---------------- concat hidden || encoder -> g_x ----------------
__global__ void concat_x(const float* __restrict__ hid, const float* __restrict__ enc) {
    int i = blockIdx.x * 256 + threadIdx.x;          // float4 index
    const int n_img = S_IMG * DIM / 4;
    float4* xo = reinterpret_cast<float4*>(g_x);
    if (i < n_img) xo[i] = reinterpret_cast<const float4*>(hid)[i];
    else           xo[i] = reinterpret_cast<const float4*>(enc)[i - n_img];
}

// ---------------- SGEMM: C[M,N] = A[M,K] @ B[K,N] + bias ----------------
// 128x128 block tile, BK=16, 256 threads, 8x8 per-thread microtile.
__global__ __launch_bounds__(256) void sgemm_bias(
    const float* __restrict__ A, const float* __restrict__ B,
    const float* __restrict__ bias, float* __restrict__ C,
    int M, int N, int K)
{
    __shared__ float As[16][132];   // [k][m], padded
    __shared__ float Bs[16][128];   // [k][n]
    const int t  = threadIdx.x;
    const int tr = t >> 4;          // 0..15
    const int tc = t & 15;          // 0..15
    const int row0 = blockIdx.y * 128;
    const int col0 = blockIdx.x * 128;

    float acc[8][8];
    #pragma unroll
    for (int i = 0; i < 8; i++)
        #pragma unroll
        for (int j = 0; j < 8; j++) acc[i][j] = 0.0f;

    for (int k0 = 0; k0 < K; k0 += 16) {
        #pragma unroll
        for (int i = 0; i < 2; i++) {
            int p = t * 2 + i;                      // 0..511
            int ar = p >> 2, ak = (p & 3) * 4;      // A tile: 128 rows x 16 k
            float4 av = *reinterpret_cast<const float4*>(&A[(size_t)(row0 + ar) * K + k0 + ak]);
            As[ak + 0][ar] = av.x; As[ak + 1][ar] = av.y;
            As[ak + 2][ar] = av.z; As[ak + 3][ar] = av.w;
            int br = p >> 5, bc = (p & 31) * 4;     // B tile: 16 rows x 128 n
            *reinterpret_cast<float4*>(&Bs[br][bc]) =
                *reinterpret_cast<const float4*>(&B[(size_t)(k0 + br) * N + col0 + bc]);
        }
        __syncthreads();
        #pragma unroll
        for (int kk = 0; kk < 16; kk++) {
            float a[8], b[8];
            *reinterpret_cast<float4*>(&a[0]) = *reinterpret_cast<float4*>(&As[kk][tr * 8]);
            *reinterpret_cast<float4*>(&a[4]) = *reinterpret_cast<float4*>(&As[kk][tr * 8 + 4]);
            *reinterpret_cast<float4*>(&b[0]) = *reinterpret_cast<float4*>(&Bs[kk][tc * 8]);
            *reinterpret_cast<float4*>(&b[4]) = *reinterpret_cast<float4*>(&Bs[kk][tc * 8 + 4]);
            #pragma unroll
            for (int i = 0; i < 8; i++)
                #pragma unroll
                for (int j = 0; j < 8; j++) acc[i][j] += a[i] * b[j];
        }
        __syncthreads();
    }

    #pragma unroll
    for (int i = 0; i < 8; i++) {
        int row = row0 + tr * 8 + i;
        #pragma unroll
        for (int j4 = 0; j4 < 8; j4 += 4) {
            int col = col0 + tc * 8 + j4;
            float4 o;
            o.x = acc[i][j4 + 0] + bias[col + 0];
            o.y = acc[i][j4 + 1] + bias[col + 1];
            o.z = acc[i][j4 + 2] + bias[col + 2];
            o.w = acc[i][j4 + 3] + bias[col + 3];
            *reinterpret_cast<float4*>(&C[(size_t)row * N + col]) = o;
        }
    }
}

// ---------------- per-head RMSNorm + RoPE (in place) ----------------
// grid (SEQ, HEADS), 128 threads = one head-row.
__global__ __launch_bounds__(128) void norm_rope(
    float* __restrict__ buf, const float* __restrict__ w,
    const float* __restrict__ rc, const float* __restrict__ rs)
{
    const int s = blockIdx.x, h = blockIdx.y, t = threadIdx.x;
    float* p = buf + (size_t)s * DIM + h * HD;
    float x = p[t];
    float ss = x * x;
    #pragma unroll
    for (int off = 16; off; off >>= 1) ss += __shfl_xor_sync(0xffffffffu, ss, off);
    __shared__ float wsum[4];
    if ((t & 31) == 0) wsum[t >> 5] = ss;
    __syncthreads();
    float tot = wsum[0] + wsum[1] + wsum[2] + wsum[3];
    float r = rsqrtf(tot * (1.0f / HD) + 1e-6f);
    float val = x * r * w[t];
    if (s < S_IMG) {
        float prt = __shfl_xor_sync(0xffffffffu, val, 1);
        float rot = (t & 1) ? prt : -prt;      // rot[2i]=-x[2i+1], rot[2i+1]=x[2i]
        val = val * rc[s * HD + t] + rot * rs[s * HD + t];
    }
    p[t] = val;
}

// ---------------- flash attention (online softmax) ----------------
// grid (SEQ/64, HEADS), 256 threads. 64-row Q tile, 64-row K/V tiles.
#define ATTN_SMEM ((128 * 68 * 2 + 64 * 128 + 64 * 68) * 4)

__global__ __launch_bounds__(256) void attn_kernel() {
    extern __shared__ float sm[];
    float* Qs = sm;                    // [128][68] (d-major, transposed)
    float* Ks = Qs + 128 * 68;         // [128][68]
    float* Vs = Ks + 128 * 68;         // [64][128]
    float* Ps = Vs + 64 * 128;         // [64][68]  (col-major P for PV)

    const int t  = threadIdx.x;
    const int tr = t >> 4;             // S rows tr*4..+3
    const int tc = t & 15;             // S cols tc*4..+3 ; O cols tc*8..+7
    const int h  = blockIdx.y;
    const int q0 = blockIdx.x * 64;
    const float scale = 0.08838834764831845f;   // 1/sqrt(128)

    #pragma unroll
    for (int i = 0; i < 8; i++) {
        int p = t + i * 256;
        int r = p >> 5, d = (p & 31) * 4;
        float4 v = *reinterpret_cast<const float4*>(&g_q[(size_t)(q0 + r) * DIM + h * HD + d]);
        Qs[(d + 0) * 68 + r] = v.x * scale; Qs[(d + 1) * 68 + r] = v.y * scale;
        Qs[(d + 2) * 68 + r] = v.z * scale; Qs[(d + 3) * 68 + r] = v.w * scale;
    }

    float m[4], l[4], O[4][8];
    #pragma unroll
    for (int i = 0; i < 4; i++) {
        m[i] = -INFINITY; l[i] = 0.0f;
        #pragma unroll
        for (int c = 0; c < 8; c++) O[i][c] = 0.0f;
    }

    for (int k0 = 0; k0 < SEQ; k0 += 64) {
        #pragma unroll
        for (int i = 0; i < 8; i++) {
            int p = t + i * 256;
            int r = p >> 5, d = (p & 31) * 4;
            float4 kv = *reinterpret_cast<const float4*>(&g_k[(size_t)(k0 + r) * DIM + h * HD + d]);
            Ks[(d + 0) * 68 + r] = kv.x; Ks[(d + 1) * 68 + r] = kv.y;
            Ks[(d + 2) * 68 + r] = kv.z; Ks[(d + 3) * 68 + r] = kv.w;
            *reinterpret_cast<float4*>(&Vs[r * 128 + d]) =
                *reinterpret_cast<const float4*>(&g_v[(size_t)(k0 + r) * DIM + h * HD + d]);
        }
        __syncthreads();

        float acc[4][4] = {};
        #pragma unroll 16
        for (int d = 0; d < 128; d++) {
            float4 a = *reinterpret_cast<float4*>(&Qs[d * 68 + tr * 4]);
            float4 b = *reinterpret_cast<float4*>(&Ks[d * 68 + tc * 4]);
            acc[0][0] += a.x * b.x; acc[0][1] += a.x * b.y; acc[0][2] += a.x * b.z; acc[0][3] += a.x * b.w;
            acc[1][0] += a.y * b.x; acc[1][1] += a.y * b.y; acc[1][2] += a.y * b.z; acc[1][3] += a.y * b.w;
            acc[2][0] += a.z * b.x; acc[2][1] += a.z * b.y; acc[2][2] += a.z * b.z; acc[2][3] += a.z * b.w;
            acc[3][0] += a.w * b.x; acc[3][1] += a.w * b.y; acc[3][2] += a.w * b.z; acc[3][3] += a.w * b.w;
        }

        #pragma unroll
        for (int i = 0; i < 4; i++) {
            float rm = fmaxf(fmaxf(acc[i][0], acc[i][1]), fmaxf(acc[i][2], acc[i][3]));
            #pragma unroll
            for (int off = 8; off; off >>= 1) rm = fmaxf(rm, __shfl_xor_sync(0xffffffffu, rm, off));
            float mn = fmaxf(m[i], rm);
            float al = __expf(m[i] - mn);
            float rsum = 0.0f;
            #pragma unroll
            for (int j = 0; j < 4; j++) { acc[i][j] = __expf(acc[i][j] - mn); rsum += acc[i][j]; }
            #pragma unroll
            for (int off = 8; off; off >>= 1) rsum += __shfl_xor_sync(0xffffffffu, rsum, off);
            l[i] = l[i] * al + rsum;
            m[i] = mn;
            #pragma unroll
            for (int c = 0; c < 8; c++) O[i][c] *= al;
        }

        #pragma unroll
        for (int j = 0; j < 4; j++)
            *reinterpret_cast<float4*>(&Ps[(tc * 4 + j) * 68 + tr * 4]) =
                make_float4(acc[0][j], acc[1][j], acc[2][j], acc[3][j]);
        __syncthreads();

        #pragma unroll 8
        for (int j = 0; j < 64; j++) {
            float4 p4 = *reinterpret_cast<float4*>(&Ps[j * 68 + tr * 4]);
            float4 v0 = *reinterpret_cast<float4*>(&Vs[j * 128 + tc * 8]);
            float4 v1 = *reinterpret_cast<float4*>(&Vs[j * 128 + tc * 8 + 4]);
            O[0][0] += p4.x * v0.x; O[0][1] += p4.x * v0.y; O[0][2] += p4.x * v0.z; O[0][3] += p4.x * v0.w;
            O[0][4] += p4.x * v1.x; O[0][5] += p4.x * v1.y; O[0][6] += p4.x * v1.z; O[0][7] += p4.x * v1.w;
            O[1][0] += p4.y * v0.x; O[1][1] += p4.y * v0.y; O[1][2] += p4.y * v0.z; O[1][3] += p4.y * v0.w;
            O[1][4] += p4.y * v1.x; O[1][5] += p4.y * v1.y; O[1][6] += p4.y * v1.z; O[1][7] += p4.y * v1.w;
            O[2][0] += p4.z * v0.x; O[2][1] += p4.z * v0.y; O[2][2] += p4.z * v0.z; O[2][3] += p4.z * v0.w;
            O[2][4] += p4.z * v1.x; O[2][5] += p4.z * v1.y; O[2][6] += p4.z * v1.z; O[2][7] += p4.z * v1.w;
            O[3][0] += p4.w * v0.x; O[3][1] += p4.w * v0.y; O[3][2] += p4.w * v0.z; O[3][3] += p4.w * v0.w;
            O[3][4] += p4.w * v1.x; O[3][5] += p4.w * v1.y; O[3][6] += p4.w * v1.z; O[3][7] += p4.w * v1.w;
        }
        __syncthreads();
    }

    #pragma unroll
    for (int i = 0; i < 4; i++) {
        float inv = 1.0f / l[i];
        int s = q0 + tr * 4 + i;
        float4 o0 = make_float4(O[i][0] * inv, O[i][1] * inv, O[i][2] * inv, O[i][3] * inv);
        float4 o1 = make_float4(O[i][4] * inv, O[i][5] * inv, O[i][6] * inv, O[i][7] * inv);
        *reinterpret_cast<float4*>(&g_attn[(size_t)s * DIM + h * HD + tc * 8])     = o0;
        *reinterpret_cast<float4*>(&g_attn[(size_t)s * DIM + h * HD + tc * 8 + 4]) = o1;
    }
}

// ---------------- txt rows pass through unprojected ----------------
__global__ void copy_txt(float* __restrict__ out) {
    int i = blockIdx.x * 256 + threadIdx.x;   // float4 index over S_TXT*DIM
    reinterpret_cast<float4*>(out + (size_t)S_IMG * DIM)[i] =
        reinterpret_cast<const float4*>(g_attn + (size_t)S_IMG * DIM)[i];
}

// ---------------- launch ----------------
extern "C" void kernel_launch(void* const* d_in, const int* in_sizes, int n_in,
                              void* d_out, int out_size) {
    const float* hid  = (const float*)d_in[0];
    const float* enc  = (const float*)d_in[1];
    const float* rcos = (const float*)d_in[2];
    const float* rsin = (const float*)d_in[3];
    const float* Wq   = (const float*)d_in[4];
    const float* bq   = (const float*)d_in[5];
    const float* Wk   = (const float*)d_in[6];
    const float* bk   = (const float*)d_in[7];
    const float* Wv   = (const float*)d_in[8];
    const float* bv   = (const float*)d_in[9];
    const float* nqw  = (const float*)d_in[10];
    const float* nkw  = (const float*)d_in[11];
    const float* Wo   = (const float*)d_in[12];
    const float* bo   = (const float*)d_in[13];
    float* out = (float*)d_out;

    float *px, *pq, *pk, *pv, *pa;
    cudaGetSymbolAddress((void**)&px, g_x);
    cudaGetSymbolAddress((void**)&pq, g_q);
    cudaGetSymbolAddress((void**)&pk, g_k);
    cudaGetSymbolAddress((void**)&pv, g_v);
    cudaGetSymbolAddress((void**)&pa, g_attn);

    cudaFuncSetAttribute(attn_kernel, cudaFuncAttributeMaxDynamicSharedMemorySize, ATTN_SMEM);

    concat_x<<<SEQ * DIM / 1024, 256>>>(hid, enc);

    dim3 gqkv(DIM / 128, SEQ / 128);
    sgemm_bias<<<gqkv, 256>>>(px, Wq, bq, pq, SEQ, DIM, DIM);
    sgemm_bias<<<gqkv, 256>>>(px, Wk, bk, pk, SEQ, DIM, DIM);
    sgemm_bias<<<gqkv, 256>>>(px, Wv, bv, pv, SEQ, DIM, DIM);

    dim3 gn(SEQ, HEADS);
    norm_rope<<<gn, 128>>>(pq, nqw, rcos, rsin);
    norm_rope<<<gn, 128>>>(pk, nkw, rcos, rsin);

    dim3 ga(SEQ / 64, HEADS);
    attn_kernel<<<ga, 256, ATTN_SMEM>>>();

    dim3 gout(DIM / 128, S_IMG / 128);
    sgemm_bias<<<gout, 256>>>(pa, Wo, bo, out, S_IMG, DIM, DIM);

    copy_txt<<<S_TXT * DIM / 1024, 256>>>(out);
}

// round 2
// speedup vs baseline: 1.7708x; 1.7708x over previous
#include <cuda_runtime.h>
#include <math.h>
#include <stdint.h>

#define S_IMG 2048
#define S_TXT 256
#define SEQ   2304
#define DIM   3072
#define HEADS 24
#define HD    128

// ---------------- scratch (device globals: allocation-free) ----------------
__device__ float g_x[SEQ * DIM];
__device__ float g_q[SEQ * DIM];
__device__ float g_k[SEQ * DIM];
__device__ float g_v[SEQ * DIM];
__device__ float g_attn[SEQ * DIM];
__device__ float g_wq[DIM * DIM];
__device__ float g_wk[DIM * DIM];
__device__ float g_wv[DIM * DIM];
__device__ float g_wo[DIM * DIM];

__device__ __forceinline__ float tf32r(float x) {
    uint32_t u;
    asm("cvt.rna.tf32.f32 %0, %1;" : "=r"(u) : "f"(x));
    return __uint_as_float(u);
}

// ---------------- concat hidden || encoder -> g_x (tf32-rounded) ----------------
__global__ void concat_x(const float* __restrict__ hid, const float* __restrict__ enc) {
    int i = blockIdx.x * 256 + threadIdx.x;          // float4 index
    const int n_img = S_IMG * DIM / 4;
    float4 v = (i < n_img) ? reinterpret_cast<const float4*>(hid)[i]
                           : reinterpret_cast<const float4*>(enc)[i - n_img];
    v.x = tf32r(v.x); v.y = tf32r(v.y); v.z = tf32r(v.z); v.w = tf32r(v.w);
    reinterpret_cast<float4*>(g_x)[i] = v;
}

// ---------------- round a weight matrix to tf32 ----------------
__global__ void round_w(const float* __restrict__ src, float* __restrict__ dst) {
    int i = blockIdx.x * 256 + threadIdx.x;          // float4 index, n = DIM*DIM/4
    float4 v = reinterpret_cast<const float4*>(src)[i];
    v.x = tf32r(v.x); v.y = tf32r(v.y); v.z = tf32r(v.z); v.w = tf32r(v.w);
    reinterpret_cast<float4*>(dst)[i] = v;
}

// ---------------- tf32 tensor-core GEMM: C = A @ B + bias ----------------
// 128x128 tile, BK=32, 256 threads = 2x4 warps, warp tile 64x32 (4x4 m16n8k8).
// A,B must already be tf32-rounded. 2-stage cp.async pipeline.
#define GEMM_STAGE_FLOATS (128 * 36 + 32 * 136)      // 8960
#define GEMM_SMEM (2 * GEMM_STAGE_FLOATS * 4)        // 71680 bytes

__device__ __forceinline__ void cpasync16(uint32_t s, const float* g) {
    asm volatile("cp.async.cg.shared.global [%0], [%1], 16;" :: "r"(s), "l"(g));
}

__global__ __launch_bounds__(256) void gemm_tf32(
    const float* __restrict__ A, const float* __restrict__ B,
    const float* __restrict__ bias, float* __restrict__ C,
    int M, int N, int K)
{
    extern __shared__ float smbuf[];
    const int t    = threadIdx.x;
    const int lane = t & 31, warp = t >> 5;
    const int wm   = (warp >> 2) * 64;
    const int wn   = (warp & 3) * 32;
    const int grp  = lane >> 2, kq = lane & 3;
    const int row0 = blockIdx.y * 128, col0 = blockIdx.x * 128;
    const int KT   = K / 32;

    float c[4][4][4];
    #pragma unroll
    for (int mi = 0; mi < 4; mi++)
        #pragma unroll
        for (int ni = 0; ni < 4; ni++)
            #pragma unroll
            for (int r = 0; r < 4; r++) c[mi][ni][r] = 0.0f;

    uint32_t sbase = (uint32_t)__cvta_generic_to_shared(smbuf);

    // prologue: prefetch k-tile 0 into stage 0
    {
        uint32_t sa = sbase, sb = sbase + 4608 * 4;
        #pragma unroll
        for (int i = 0; i < 4; i++) {
            int p = t + i * 256;
            int ar = p >> 3, ak = (p & 7) * 4;
            cpasync16(sa + (ar * 36 + ak) * 4, &A[(size_t)(row0 + ar) * K + ak]);
            int br = p >> 5, bc = (p & 31) * 4;
            cpasync16(sb + (br * 136 + bc) * 4, &B[(size_t)br * N + col0 + bc]);
        }
        asm volatile("cp.async.commit_group;");
    }

    for (int kt = 0; kt < KT; kt++) {
        asm volatile("cp.async.wait_group 0;");
        __syncthreads();

        if (kt + 1 < KT) {
            int st = (kt + 1) & 1;
            int k0 = (kt + 1) * 32;
            uint32_t sa = sbase + st * GEMM_STAGE_FLOATS * 4;
            uint32_t sb = sa + 4608 * 4;
            #pragma unroll
            for (int i = 0; i < 4; i++) {
                int p = t + i * 256;
                int ar = p >> 3, ak = (p & 7) * 4;
                cpasync16(sa + (ar * 36 + ak) * 4, &A[(size_t)(row0 + ar) * K + k0 + ak]);
                int br = p >> 5, bc = (p & 31) * 4;
                cpasync16(sb + (br * 136 + bc) * 4, &B[(size_t)(k0 + br) * N + col0 + bc]);
            }
            asm volatile("cp.async.commit_group;");
        }

        const float* as = smbuf + (kt & 1) * GEMM_STAGE_FLOATS;
        const float* bs = as + 4608;

        #pragma unroll
        for (int ks = 0; ks < 4; ks++) {
            const int kb = ks * 8;
            uint32_t af[4][4], bf[4][2];
            #pragma unroll
            for (int mi = 0; mi < 4; mi++) {
                int r = wm + mi * 16 + grp;
                af[mi][0] = __float_as_uint(as[r * 36 + kb + kq]);
                af[mi][1] = __float_as_uint(as[(r + 8) * 36 + kb + kq]);
                af[mi][2] = __float_as_uint(as[r * 36 + kb + kq + 4]);
                af[mi][3] = __float_as_uint(as[(r + 8) * 36 + kb + kq + 4]);
            }
            #pragma unroll
            for (int ni = 0; ni < 4; ni++) {
                int cl = wn + ni * 8 + grp;
                bf[ni][0] = __float_as_uint(bs[(kb + kq) * 136 + cl]);
                bf[ni][1] = __float_as_uint(bs[(kb + kq + 4) * 136 + cl]);
            }
            #pragma unroll
            for (int mi = 0; mi < 4; mi++)
                #pragma unroll
                for (int ni = 0; ni < 4; ni++)
                    asm volatile(
                        "mma.sync.aligned.m16n8k8.row.col.f32.tf32.tf32.f32 "
                        "{%0,%1,%2,%3},{%4,%5,%6,%7},{%8,%9},{%0,%1,%2,%3};"
                        : "+f"(c[mi][ni][0]), "+f"(c[mi][ni][1]),
                          "+f"(c[mi][ni][2]), "+f"(c[mi][ni][3])
                        : "r"(af[mi][0]), "r"(af[mi][1]), "r"(af[mi][2]), "r"(af[mi][3]),
                          "r"(bf[ni][0]), "r"(bf[ni][1]));
        }
        __syncthreads();
    }

    #pragma unroll
    for (int mi = 0; mi < 4; mi++) {
        int r = row0 + wm + mi * 16 + grp;
        #pragma unroll
        for (int ni = 0; ni < 4; ni++) {
            int cc = col0 + wn + ni * 8 + 2 * kq;
            float2 bsv = *reinterpret_cast<const float2*>(&bias[cc]);
            float2 o0 = make_float2(c[mi][ni][0] + bsv.x, c[mi][ni][1] + bsv.y);
            float2 o1 = make_float2(c[mi][ni][2] + bsv.x, c[mi][ni][3] + bsv.y);
            *reinterpret_cast<float2*>(&C[(size_t)r * N + cc]) = o0;
            *reinterpret_cast<float2*>(&C[(size_t)(r + 8) * N + cc]) = o1;
        }
    }
}

// ---------------- per-head RMSNorm + RoPE (in place) ----------------
__global__ __launch_bounds__(128) void norm_rope(
    float* __restrict__ buf, const float* __restrict__ w,
    const float* __restrict__ rc, const float* __restrict__ rs)
{
    const int s = blockIdx.x, h = blockIdx.y, t = threadIdx.x;
    float* p = buf + (size_t)s * DIM + h * HD;
    float x = p[t];
    float ss = x * x;
    #pragma unroll
    for (int off = 16; off; off >>= 1) ss += __shfl_xor_sync(0xffffffffu, ss, off);
    __shared__ float wsum[4];
    if ((t & 31) == 0) wsum[t >> 5] = ss;
    __syncthreads();
    float tot = wsum[0] + wsum[1] + wsum[2] + wsum[3];
    float r = rsqrtf(tot * (1.0f / HD) + 1e-6f);
    float val = x * r * w[t];
    if (s < S_IMG) {
        float prt = __shfl_xor_sync(0xffffffffu, val, 1);
        float rot = (t & 1) ? prt : -prt;
        val = val * rc[s * HD + t] + rot * rs[s * HD + t];
    }
    p[t] = val;
}

// ---------------- flash attention (online softmax, fp32 SIMT) ----------------
#define ATTN_SMEM ((128 * 68 * 2 + 64 * 128 + 64 * 68) * 4)

__global__ __launch_bounds__(256) void attn_kernel() {
    extern __shared__ float sm[];
    float* Qs = sm;                    // [128][68] (d-major)
    float* Ks = Qs + 128 * 68;         // [128][68]
    float* Vs = Ks + 128 * 68;         // [64][128]
    float* Ps = Vs + 64 * 128;         // [64][68]

    const int t  = threadIdx.x;
    const int tr = t >> 4;
    const int tc = t & 15;
    const int h  = blockIdx.y;
    const int q0 = blockIdx.x * 64;
    const float scale = 0.08838834764831845f;
    const bool rnd = (q0 < S_IMG);     // rows feeding the Wo GEMM get tf32-rounded

    #pragma unroll
    for (int i = 0; i < 8; i++) {
        int p = t + i * 256;
        int r = p >> 5, d = (p & 31) * 4;
        float4 v = *reinterpret_cast<const float4*>(&g_q[(size_t)(q0 + r) * DIM + h * HD + d]);
        Qs[(d + 0) * 68 + r] = v.x * scale; Qs[(d + 1) * 68 + r] = v.y * scale;
        Qs[(d + 2) * 68 + r] = v.z * scale; Qs[(d + 3) * 68 + r] = v.w * scale;
    }

    float m[4], l[4], O[4][8];
    #pragma unroll
    for (int i = 0; i < 4; i++) {
        m[i] = -INFINITY; l[i] = 0.0f;
        #pragma unroll
        for (int c = 0; c < 8; c++) O[i][c] = 0.0f;
    }

    for (int k0 = 0; k0 < SEQ; k0 += 64) {
        #pragma unroll
        for (int i = 0; i < 8; i++) {
            int p = t + i * 256;
            int r = p >> 5, d = (p & 31) * 4;
            float4 kv = *reinterpret_cast<const float4*>(&g_k[(size_t)(k0 + r) * DIM + h * HD + d]);
            Ks[(d + 0) * 68 + r] = kv.x; Ks[(d + 1) * 68 + r] = kv.y;
            Ks[(d + 2) * 68 + r] = kv.z; Ks[(d + 3) * 68 + r] = kv.w;
            *reinterpret_cast<float4*>(&Vs[r * 128 + d]) =
                *reinterpret_cast<const float4*>(&g_v[(size_t)(k0 + r) * DIM + h * HD + d]);
        }
        __syncthreads();

        float acc[4][4] = {};
        #pragma unroll 16
        for (int d = 0; d < 128; d++) {
            float4 a = *reinterpret_cast<float4*>(&Qs[d * 68 + tr * 4]);
            float4 b = *reinterpret_cast<float4*>(&Ks[d * 68 + tc * 4]);
            acc[0][0] += a.x * b.x; acc[0][1] += a.x * b.y; acc[0][2] += a.x * b.z; acc[0][3] += a.x * b.w;
            acc[1][0] += a.y * b.x; acc[1][1] += a.y * b.y; acc[1][2] += a.y * b.z; acc[1][3] += a.y * b.w;
            acc[2][0] += a.z * b.x; acc[2][1] += a.z * b.y; acc[2][2] += a.z * b.z; acc[2][3] += a.z * b.w;
            acc[3][0] += a.w * b.x; acc[3][1] += a.w * b.y; acc[3][2] += a.w * b.z; acc[3][3] += a.w * b.w;
        }

        #pragma unroll
        for (int i = 0; i < 4; i++) {
            float rm = fmaxf(fmaxf(acc[i][0], acc[i][1]), fmaxf(acc[i][2], acc[i][3]));
            #pragma unroll
            for (int off = 8; off; off >>= 1) rm = fmaxf(rm, __shfl_xor_sync(0xffffffffu, rm, off));
            float mn = fmaxf(m[i], rm);
            float al = __expf(m[i] - mn);
            float rsum = 0.0f;
            #pragma unroll
            for (int j = 0; j < 4; j++) { acc[i][j] = __expf(acc[i][j] - mn); rsum += acc[i][j]; }
            #pragma unroll
            for (int off = 8; off; off >>= 1) rsum += __shfl_xor_sync(0xffffffffu, rsum, off);
            l[i] = l[i] * al + rsum;
            m[i] = mn;
            #pragma unroll
            for (int c = 0; c < 8; c++) O[i][c] *= al;
        }

        #pragma unroll
        for (int j = 0; j < 4; j++)
            *reinterpret_cast<float4*>(&Ps[(tc * 4 + j) * 68 + tr * 4]) =
                make_float4(acc[0][j], acc[1][j], acc[2][j], acc[3][j]);
        __syncthreads();

        #pragma unroll 8
        for (int j = 0; j < 64; j++) {
            float4 p4 = *reinterpret_cast<float4*>(&Ps[j * 68 + tr * 4]);
            float4 v0 = *reinterpret_cast<float4*>(&Vs[j * 128 + tc * 8]);
            float4 v1 = *reinterpret_cast<float4*>(&Vs[j * 128 + tc * 8 + 4]);
            O[0][0] += p4.x * v0.x; O[0][1] += p4.x * v0.y; O[0][2] += p4.x * v0.z; O[0][3] += p4.x * v0.w;
            O[0][4] += p4.x * v1.x; O[0][5] += p4.x * v1.y; O[0][6] += p4.x * v1.z; O[0][7] += p4.x * v1.w;
            O[1][0] += p4.y * v0.x; O[1][1] += p4.y * v0.y; O[1][2] += p4.y * v0.z; O[1][3] += p4.y * v0.w;
            O[1][4] += p4.y * v1.x; O[1][5] += p4.y * v1.y; O[1][6] += p4.y * v1.z; O[1][7] += p4.y * v1.w;
            O[2][0] += p4.z * v0.x; O[2][1] += p4.z * v0.y; O[2][2] += p4.z * v0.z; O[2][3] += p4.z * v0.w;
            O[2][4] += p4.z * v1.x; O[2][5] += p4.z * v1.y; O[2][6] += p4.z * v1.z; O[2][7] += p4.z * v1.w;
            O[3][0] += p4.w * v0.x; O[3][1] += p4.w * v0.y; O[3][2] += p4.w * v0.z; O[3][3] += p4.w * v0.w;
            O[3][4] += p4.w * v1.x; O[3][5] += p4.w * v1.y; O[3][6] += p4.w * v1.z; O[3][7] += p4.w * v1.w;
        }
        __syncthreads();
    }

    #pragma unroll
    for (int i = 0; i < 4; i++) {
        float inv = 1.0f / l[i];
        int s = q0 + tr * 4 + i;
        float o[8];
        #pragma unroll
        for (int c = 0; c < 8; c++) {
            o[c] = O[i][c] * inv;
            if (rnd) o[c] = tf32r(o[c]);
        }
        *reinterpret_cast<float4*>(&g_attn[(size_t)s * DIM + h * HD + tc * 8]) =
            make_float4(o[0], o[1], o[2], o[3]);
        *reinterpret_cast<float4*>(&g_attn[(size_t)s * DIM + h * HD + tc * 8 + 4]) =
            make_float4(o[4], o[5], o[6], o[7]);
    }
}

// ---------------- txt rows pass through unprojected ----------------
__global__ void copy_txt(float* __restrict__ out) {
    int i = blockIdx.x * 256 + threadIdx.x;
    reinterpret_cast<float4*>(out + (size_t)S_IMG * DIM)[i] =
        reinterpret_cast<const float4*>(g_attn + (size_t)S_IMG * DIM)[i];
}

// ---------------- launch ----------------
extern "C" void kernel_launch(void* const* d_in, const int* in_sizes, int n_in,
                              void* d_out, int out_size) {
    const float* hid  = (const float*)d_in[0];
    const float* enc  = (const float*)d_in[1];
    const float* rcos = (const float*)d_in[2];
    const float* rsin = (const float*)d_in[3];
    const float* Wq   = (const float*)d_in[4];
    const float* bq   = (const float*)d_in[5];
    const float* Wk   = (const float*)d_in[6];
    const float* bk   = (const float*)d_in[7];
    const float* Wv   = (const float*)d_in[8];
    const float* bv   = (const float*)d_in[9];
    const float* nqw  = (const float*)d_in[10];
    const float* nkw  = (const float*)d_in[11];
    const float* Wo   = (const float*)d_in[12];
    const float* bo   = (const float*)d_in[13];
    float* out = (float*)d_out;

    float *px, *pq, *pk, *pv, *pa, *pwq, *pwk, *pwv, *pwo;
    cudaGetSymbolAddress((void**)&px, g_x);
    cudaGetSymbolAddress((void**)&pq, g_q);
    cudaGetSymbolAddress((void**)&pk, g_k);
    cudaGetSymbolAddress((void**)&pv, g_v);
    cudaGetSymbolAddress((void**)&pa, g_attn);
    cudaGetSymbolAddress((void**)&pwq, g_wq);
    cudaGetSymbolAddress((void**)&pwk, g_wk);
    cudaGetSymbolAddress((void**)&pwv, g_wv);
    cudaGetSymbolAddress((void**)&pwo, g_wo);

    cudaFuncSetAttribute(attn_kernel, cudaFuncAttributeMaxDynamicSharedMemorySize, ATTN_SMEM);
    cudaFuncSetAttribute(gemm_tf32, cudaFuncAttributeMaxDynamicSharedMemorySize, GEMM_SMEM);

    concat_x<<<SEQ * DIM / 1024, 256>>>(hid, enc);

    const int nw4 = DIM * DIM / 1024;
    round_w<<<nw4, 256>>>(Wq, pwq);
    round_w<<<nw4, 256>>>(Wk, pwk);
    round_w<<<nw4, 256>>>(Wv, pwv);
    round_w<<<nw4, 256>>>(Wo, pwo);

    dim3 gqkv(DIM / 128, SEQ / 128);
    gemm_tf32<<<gqkv, 256, GEMM_SMEM>>>(px, pwq, bq, pq, SEQ, DIM, DIM);
    gemm_tf32<<<gqkv, 256, GEMM_SMEM>>>(px, pwk, bk, pk, SEQ, DIM, DIM);
    gemm_tf32<<<gqkv, 256, GEMM_SMEM>>>(px, pwv, bv, pv, SEQ, DIM, DIM);

    dim3 gn(SEQ, HEADS);
    norm_rope<<<gn, 128>>>(pq, nqw, rcos, rsin);
    norm_rope<<<gn, 128>>>(pk, nkw, rcos, rsin);

    dim3 ga(SEQ / 64, HEADS);
    attn_kernel<<<ga, 256, ATTN_SMEM>>>();

    dim3 gout(DIM / 128, S_IMG / 128);
    gemm_tf32<<<gout, 256, GEMM_SMEM>>>(pa, pwo, bo, out, S_IMG, DIM, DIM);

    copy_txt<<<S_TXT * DIM / 1024, 256>>>(out);
}

// round 3
// speedup vs baseline: 3.4332x; 1.9388x over previous
#include <cuda_runtime.h>
#include <cuda_fp16.h>
#include <math.h>
#include <stdint.h>

#define S_IMG 2048
#define S_TXT 256
#define SEQ   2304
#define DIM   3072
#define HEADS 24
#define HD    128

#define QSCALE 0.12751743f   // (1/sqrt(128)) * log2(e)

// ---------------- scratch (device globals: allocation-free) ----------------
__device__ float g_x[SEQ * DIM];
__device__ float g_q[SEQ * DIM];
__device__ float g_k[SEQ * DIM];
__device__ float g_v[SEQ * DIM];
__device__ float g_attn[SEQ * DIM];
__device__ float g_wq[DIM * DIM];
__device__ float g_wk[DIM * DIM];
__device__ float g_wv[DIM * DIM];
__device__ float g_wo[DIM * DIM];
__device__ __half g_qh[SEQ * DIM];
__device__ __half g_ql[SEQ * DIM];
__device__ __half g_kh[SEQ * DIM];
__device__ __half g_kl[SEQ * DIM];
__device__ __half g_vh[SEQ * DIM];

__device__ __forceinline__ float tf32r(float x) {
    uint32_t u;
    asm("cvt.rna.tf32.f32 %0, %1;" : "=r"(u) : "f"(x));
    return __uint_as_float(u);
}
__device__ __forceinline__ float ex2(float x) {
    float r;
    asm("ex2.approx.f32 %0, %1;" : "=f"(r) : "f"(x));
    return r;
}
__device__ __forceinline__ void cpasync16(uint32_t s, const void* g) {
    asm volatile("cp.async.cg.shared.global [%0], [%1], 16;" :: "r"(s), "l"(g));
}
__device__ __forceinline__ void mma_f16(float* c, const uint32_t* a, const uint32_t* b) {
    asm volatile("mma.sync.aligned.m16n8k16.row.col.f32.f16.f16.f32 "
        "{%0,%1,%2,%3},{%4,%5,%6,%7},{%8,%9},{%0,%1,%2,%3};"
        : "+f"(c[0]), "+f"(c[1]), "+f"(c[2]), "+f"(c[3])
        : "r"(a[0]), "r"(a[1]), "r"(a[2]), "r"(a[3]), "r"(b[0]), "r"(b[1]));
}
__device__ __forceinline__ uint32_t packh2(float x, float y) {
    __half2 h = __floats2half2_rn(x, y);
    return *reinterpret_cast<uint32_t*>(&h);
}

// ---------------- concat hidden || encoder -> g_x (tf32-rounded) ----------------
__global__ void concat_x(const float* __restrict__ hid, const float* __restrict__ enc) {
    int i = blockIdx.x * 256 + threadIdx.x;
    const int n_img = S_IMG * DIM / 4;
    float4 v = (i < n_img) ? reinterpret_cast<const float4*>(hid)[i]
                           : reinterpret_cast<const float4*>(enc)[i - n_img];
    v.x = tf32r(v.x); v.y = tf32r(v.y); v.z = tf32r(v.z); v.w = tf32r(v.w);
    reinterpret_cast<float4*>(g_x)[i] = v;
}

__global__ void round_w(const float* __restrict__ src, float* __restrict__ dst) {
    int i = blockIdx.x * 256 + threadIdx.x;
    float4 v = reinterpret_cast<const float4*>(src)[i];
    v.x = tf32r(v.x); v.y = tf32r(v.y); v.z = tf32r(v.z); v.w = tf32r(v.w);
    reinterpret_cast<float4*>(dst)[i] = v;
}

// ---------------- tf32 tensor-core GEMM: C = A @ B + bias ----------------
#define GEMM_STAGE_FLOATS (128 * 36 + 32 * 136)
#define GEMM_SMEM (2 * GEMM_STAGE_FLOATS * 4)

__global__ __launch_bounds__(256) void gemm_tf32(
    const float* __restrict__ A, const float* __restrict__ B,
    const float* __restrict__ bias, float* __restrict__ C,
    int M, int N, int K)
{
    extern __shared__ float smbuf[];
    const int t    = threadIdx.x;
    const int lane = t & 31, warp = t >> 5;
    const int wm   = (warp >> 2) * 64;
    const int wn   = (warp & 3) * 32;
    const int grp  = lane >> 2, kq = lane & 3;
    const int row0 = blockIdx.y * 128, col0 = blockIdx.x * 128;
    const int KT   = K / 32;

    float c[4][4][4];
    #pragma unroll
    for (int mi = 0; mi < 4; mi++)
        #pragma unroll
        for (int ni = 0; ni < 4; ni++)
            #pragma unroll
            for (int r = 0; r < 4; r++) c[mi][ni][r] = 0.0f;

    uint32_t sbase = (uint32_t)__cvta_generic_to_shared(smbuf);

    {
        uint32_t sa = sbase, sb = sbase + 4608 * 4;
        #pragma unroll
        for (int i = 0; i < 4; i++) {
            int p = t + i * 256;
            int ar = p >> 3, ak = (p & 7) * 4;
            cpasync16(sa + (ar * 36 + ak) * 4, &A[(size_t)(row0 + ar) * K + ak]);
            int br = p >> 5, bc = (p & 31) * 4;
            cpasync16(sb + (br * 136 + bc) * 4, &B[(size_t)br * N + col0 + bc]);
        }
        asm volatile("cp.async.commit_group;");
    }

    for (int kt = 0; kt < KT; kt++) {
        asm volatile("cp.async.wait_group 0;");
        __syncthreads();

        if (kt + 1 < KT) {
            int st = (kt + 1) & 1;
            int k0 = (kt + 1) * 32;
            uint32_t sa = sbase + st * GEMM_STAGE_FLOATS * 4;
            uint32_t sb = sa + 4608 * 4;
            #pragma unroll
            for (int i = 0; i < 4; i++) {
                int p = t + i * 256;
                int ar = p >> 3, ak = (p & 7) * 4;
                cpasync16(sa + (ar * 36 + ak) * 4, &A[(size_t)(row0 + ar) * K + k0 + ak]);
                int br = p >> 5, bc = (p & 31) * 4;
                cpasync16(sb + (br * 136 + bc) * 4, &B[(size_t)(k0 + br) * N + col0 + bc]);
            }
            asm volatile("cp.async.commit_group;");
        }

        const float* as = smbuf + (kt & 1) * GEMM_STAGE_FLOATS;
        const float* bs = as + 4608;

        #pragma unroll
        for (int ks = 0; ks < 4; ks++) {
            const int kb = ks * 8;
            uint32_t af[4][4], bf[4][2];
            #pragma unroll
            for (int mi = 0; mi < 4; mi++) {
                int r = wm + mi * 16 + grp;
                af[mi][0] = __float_as_uint(as[r * 36 + kb + kq]);
                af[mi][1] = __float_as_uint(as[(r + 8) * 36 + kb + kq]);
                af[mi][2] = __float_as_uint(as[r * 36 + kb + kq + 4]);
                af[mi][3] = __float_as_uint(as[(r + 8) * 36 + kb + kq + 4]);
            }
            #pragma unroll
            for (int ni = 0; ni < 4; ni++) {
                int cl = wn + ni * 8 + grp;
                bf[ni][0] = __float_as_uint(bs[(kb + kq) * 136 + cl]);
                bf[ni][1] = __float_as_uint(bs[(kb + kq + 4) * 136 + cl]);
            }
            #pragma unroll
            for (int mi = 0; mi < 4; mi++)
                #pragma unroll
                for (int ni = 0; ni < 4; ni++)
                    asm volatile(
                        "mma.sync.aligned.m16n8k8.row.col.f32.tf32.tf32.f32 "
                        "{%0,%1,%2,%3},{%4,%5,%6,%7},{%8,%9},{%0,%1,%2,%3};"
                        : "+f"(c[mi][ni][0]), "+f"(c[mi][ni][1]),
                          "+f"(c[mi][ni][2]), "+f"(c[mi][ni][3])
                        : "r"(af[mi][0]), "r"(af[mi][1]), "r"(af[mi][2]), "r"(af[mi][3]),
                          "r"(bf[ni][0]), "r"(bf[ni][1]));
        }
        __syncthreads();
    }

    #pragma unroll
    for (int mi = 0; mi < 4; mi++) {
        int r = row0 + wm + mi * 16 + grp;
        #pragma unroll
        for (int ni = 0; ni < 4; ni++) {
            int cc = col0 + wn + ni * 8 + 2 * kq;
            float2 bsv = *reinterpret_cast<const float2*>(&bias[cc]);
            float2 o0 = make_float2(c[mi][ni][0] + bsv.x, c[mi][ni][1] + bsv.y);
            float2 o1 = make_float2(c[mi][ni][2] + bsv.x, c[mi][ni][3] + bsv.y);
            *reinterpret_cast<float2*>(&C[(size_t)r * N + cc]) = o0;
            *reinterpret_cast<float2*>(&C[(size_t)(r + 8) * N + cc]) = o1;
        }
    }
}

// ---------------- per-head RMSNorm + RoPE -> split fp16 hi/lo ----------------
__global__ __launch_bounds__(128) void norm_rope_split(
    const float* __restrict__ buf, const float* __restrict__ w,
    const float* __restrict__ rc, const float* __restrict__ rs,
    __half* __restrict__ oh, __half* __restrict__ ol, float fold)
{
    const int s = blockIdx.x, h = blockIdx.y, t = threadIdx.x;
    const float* p = buf + (size_t)s * DIM + h * HD;
    float x = p[t];
    float ss = x * x;
    #pragma unroll
    for (int off = 16; off; off >>= 1) ss += __shfl_xor_sync(0xffffffffu, ss, off);
    __shared__ float wsum[4];
    if ((t & 31) == 0) wsum[t >> 5] = ss;
    __syncthreads();
    float tot = wsum[0] + wsum[1] + wsum[2] + wsum[3];
    float r = rsqrtf(tot * (1.0f / HD) + 1e-6f);
    float val = x * r * w[t];
    if (s < S_IMG) {
        float prt = __shfl_xor_sync(0xffffffffu, val, 1);
        float rot = (t & 1) ? prt : -prt;
        val = val * rc[s * HD + t] + rot * rs[s * HD + t];
    }
    float y = val * fold;
    __half hi = __float2half_rn(y);
    __half lo = __float2half_rn(y - __half2float(hi));
    size_t idx = (size_t)s * DIM + h * HD + t;
    oh[idx] = hi;
    ol[idx] = lo;
}

// ---------------- V fp32 -> fp16 ----------------
__global__ void convert_vh() {
    int i = blockIdx.x * 256 + threadIdx.x;     // float4 index
    float4 v = reinterpret_cast<const float4*>(g_v)[i];
    reinterpret_cast<__half2*>(g_vh)[2 * i]     = __floats2half2_rn(v.x, v.y);
    reinterpret_cast<__half2*>(g_vh)[2 * i + 1] = __floats2half2_rn(v.z, v.w);
}

// ---------------- tensor-core flash attention ----------------
// grid (SEQ/128, HEADS), 256 threads (8 warps x 16 rows).
// smem halves: Qh[128][136], Ql[128][136], Kh[64][136], Kl[64][136], Vt[128][72]
#define AT_QH 0
#define AT_QL 17408
#define AT_KH 34816
#define AT_KL 43520
#define AT_VT 52224
#define ATTN_SMEM ((52224 + 9216) * 2)   // 122880 bytes

__global__ __launch_bounds__(256, 1) void attn_tc() {
    extern __shared__ __half sh[];
    __half* Qh = sh + AT_QH;
    __half* Ql = sh + AT_QL;
    __half* Kh = sh + AT_KH;
    __half* Kl = sh + AT_KL;
    __half* Vt = sh + AT_VT;

    const int t = threadIdx.x, lane = t & 31, w = t >> 5;
    const int grp = lane >> 2, kq = lane & 3;
    const int h = blockIdx.y, q0 = blockIdx.x * 128, m0 = w * 16;

    uint32_t sb  = (uint32_t)__cvta_generic_to_shared(sh);
    uint32_t sqh = sb + AT_QH * 2, sql = sb + AT_QL * 2;
    uint32_t skh = sb + AT_KH * 2, skl = sb + AT_KL * 2;

    // Q prologue: 128 rows x 256B each, hi+lo
    #pragma unroll
    for (int i = 0; i < 8; i++) {
        int c = t + i * 256, r = c >> 4, off = (c & 15) * 16;
        const char* bh = (const char*)(g_qh + (size_t)(q0 + r) * DIM + h * HD) + off;
        const char* bl = (const char*)(g_ql + (size_t)(q0 + r) * DIM + h * HD) + off;
        cpasync16(sqh + r * 272 + off, bh);
        cpasync16(sql + r * 272 + off, bl);
    }
    asm volatile("cp.async.commit_group;");

    float O[16][4];
    #pragma unroll
    for (int nt = 0; nt < 16; nt++)
        #pragma unroll
        for (int r = 0; r < 4; r++) O[nt][r] = 0.0f;
    float mrow0 = -INFINITY, mrow1 = -INFINITY, lrow0 = 0.0f, lrow1 = 0.0f;

    for (int kt = 0; kt < 36; kt++) {
        const int k0 = kt * 64;
        #pragma unroll
        for (int i = 0; i < 4; i++) {
            int c = t + i * 256, r = c >> 4, off = (c & 15) * 16;
            const char* bh = (const char*)(g_kh + (size_t)(k0 + r) * DIM + h * HD) + off;
            const char* bl = (const char*)(g_kl + (size_t)(k0 + r) * DIM + h * HD) + off;
            cpasync16(skh + r * 272 + off, bh);
            cpasync16(skl + r * 272 + off, bl);
        }
        asm volatile("cp.async.commit_group;");

        // V transpose into Vt[d][s] (d rows 128, pitch 72)
        {
            int sr = t >> 3, dc = (t & 7) * 16;
            #pragma unroll
            for (int pass = 0; pass < 2; pass++) {
                int s = pass * 32 + sr;
                const __half2* src = reinterpret_cast<const __half2*>(
                    g_vh + (size_t)(k0 + s) * DIM + h * HD + dc);
                #pragma unroll
                for (int j = 0; j < 8; j++) {
                    __half2 v2 = src[j];
                    Vt[(dc + 2 * j) * 72 + s]     = __low2half(v2);
                    Vt[(dc + 2 * j + 1) * 72 + s] = __high2half(v2);
                }
            }
        }
        asm volatile("cp.async.wait_group 0;");
        __syncthreads();

        // --- S = Q Kt (split fp16 x3), logits pre-scaled by log2e ---
        float S[8][4];
        #pragma unroll
        for (int n = 0; n < 8; n++)
            #pragma unroll
            for (int r = 0; r < 4; r++) S[n][r] = 0.0f;

        #pragma unroll
        for (int ks = 0; ks < 8; ks++) {
            uint32_t ah[4], al[4];
            const __half* qb = Qh + (m0 + grp) * 136 + ks * 16 + 2 * kq;
            const __half* ql2 = Ql + (m0 + grp) * 136 + ks * 16 + 2 * kq;
            ah[0] = *(const uint32_t*)qb;
            ah[1] = *(const uint32_t*)(qb + 8 * 136);
            ah[2] = *(const uint32_t*)(qb + 8);
            ah[3] = *(const uint32_t*)(qb + 8 * 136 + 8);
            al[0] = *(const uint32_t*)ql2;
            al[1] = *(const uint32_t*)(ql2 + 8 * 136);
            al[2] = *(const uint32_t*)(ql2 + 8);
            al[3] = *(const uint32_t*)(ql2 + 8 * 136 + 8);
            #pragma unroll
            for (int n = 0; n < 8; n++) {
                const __half* kb  = Kh + (n * 8 + grp) * 136 + ks * 16 + 2 * kq;
                const __half* kb2 = Kl + (n * 8 + grp) * 136 + ks * 16 + 2 * kq;
                uint32_t bh[2], bl2[2];
                bh[0]  = *(const uint32_t*)kb;  bh[1]  = *(const uint32_t*)(kb + 8);
                bl2[0] = *(const uint32_t*)kb2; bl2[1] = *(const uint32_t*)(kb2 + 8);
                mma_f16(S[n], ah, bh);
                mma_f16(S[n], ah, bl2);
                mma_f16(S[n], al, bh);
            }
        }

        // --- online softmax (log2 domain) ---
        float mx0 = -INFINITY, mx1 = -INFINITY;
        #pragma unroll
        for (int n = 0; n < 8; n++) {
            mx0 = fmaxf(mx0, fmaxf(S[n][0], S[n][1]));
            mx1 = fmaxf(mx1, fmaxf(S[n][2], S[n][3]));
        }
        mx0 = fmaxf(mx0, __shfl_xor_sync(0xffffffffu, mx0, 1));
        mx0 = fmaxf(mx0, __shfl_xor_sync(0xffffffffu, mx0, 2));
        mx1 = fmaxf(mx1, __shfl_xor_sync(0xffffffffu, mx1, 1));
        mx1 = fmaxf(mx1, __shfl_xor_sync(0xffffffffu, mx1, 2));

        float mn0 = fmaxf(mrow0, mx0), mn1 = fmaxf(mrow1, mx1);
        float a0 = ex2(mrow0 - mn0), a1 = ex2(mrow1 - mn1);
        float rs0 = 0.0f, rs1 = 0.0f;
        #pragma unroll
        for (int n = 0; n < 8; n++) {
            S[n][0] = ex2(S[n][0] - mn0);
            S[n][1] = ex2(S[n][1] - mn0);
            S[n][2] = ex2(S[n][2] - mn1);
            S[n][3] = ex2(S[n][3] - mn1);
            rs0 += S[n][0] + S[n][1];
            rs1 += S[n][2] + S[n][3];
        }
        rs0 += __shfl_xor_sync(0xffffffffu, rs0, 1);
        rs0 += __shfl_xor_sync(0xffffffffu, rs0, 2);
        rs1 += __shfl_xor_sync(0xffffffffu, rs1, 1);
        rs1 += __shfl_xor_sync(0xffffffffu, rs1, 2);
        lrow0 = lrow0 * a0 + rs0;
        lrow1 = lrow1 * a1 + rs1;
        mrow0 = mn0; mrow1 = mn1;

        #pragma unroll
        for (int nt = 0; nt < 16; nt++) {
            O[nt][0] *= a0; O[nt][1] *= a0;
            O[nt][2] *= a1; O[nt][3] *= a1;
        }

        // --- repack P accum -> A fragments (no smem) ---
        uint32_t pa[4][4];
        #pragma unroll
        for (int ks2 = 0; ks2 < 4; ks2++) {
            pa[ks2][0] = packh2(S[2 * ks2][0],     S[2 * ks2][1]);
            pa[ks2][1] = packh2(S[2 * ks2][2],     S[2 * ks2][3]);
            pa[ks2][2] = packh2(S[2 * ks2 + 1][0], S[2 * ks2 + 1][1]);
            pa[ks2][3] = packh2(S[2 * ks2 + 1][2], S[2 * ks2 + 1][3]);
        }

        // --- O += P V ---
        #pragma unroll
        for (int ks2 = 0; ks2 < 4; ks2++) {
            #pragma unroll
            for (int nt = 0; nt < 16; nt++) {
                const __half* vb = Vt + (nt * 8 + grp) * 72 + ks2 * 16 + 2 * kq;
                uint32_t b[2];
                b[0] = *(const uint32_t*)vb;
                b[1] = *(const uint32_t*)(vb + 8);
                mma_f16(O[nt], pa[ks2], b);
            }
        }
        __syncthreads();
    }

    // --- epilogue ---
    const float inv0 = 1.0f / lrow0, inv1 = 1.0f / lrow1;
    const bool rnd = (blockIdx.x < 16);       // img rows feed the Wo tf32 GEMM
    const int r = q0 + m0 + grp;
    #pragma unroll
    for (int nt = 0; nt < 16; nt++) {
        float o0 = O[nt][0] * inv0, o1 = O[nt][1] * inv0;
        float o2 = O[nt][2] * inv1, o3 = O[nt][3] * inv1;
        if (rnd) { o0 = tf32r(o0); o1 = tf32r(o1); o2 = tf32r(o2); o3 = tf32r(o3); }
        int cc = h * HD + nt * 8 + 2 * kq;
        *reinterpret_cast<float2*>(&g_attn[(size_t)r * DIM + cc]) = make_float2(o0, o1);
        *reinterpret_cast<float2*>(&g_attn[(size_t)(r + 8) * DIM + cc]) = make_float2(o2, o3);
    }
}

// ---------------- txt rows pass through unprojected ----------------
__global__ void copy_txt(float* __restrict__ out) {
    int i = blockIdx.x * 256 + threadIdx.x;
    reinterpret_cast<float4*>(out + (size_t)S_IMG * DIM)[i] =
        reinterpret_cast<const float4*>(g_attn + (size_t)S_IMG * DIM)[i];
}

// ---------------- launch ----------------
extern "C" void kernel_launch(void* const* d_in, const int* in_sizes, int n_in,
                              void* d_out, int out_size) {
    const float* hid  = (const float*)d_in[0];
    const float* enc  = (const float*)d_in[1];
    const float* rcos = (const float*)d_in[2];
    const float* rsin = (const float*)d_in[3];
    const float* Wq   = (const float*)d_in[4];
    const float* bq   = (const float*)d_in[5];
    const float* Wk   = (const float*)d_in[6];
    const float* bk   = (const float*)d_in[7];
    const float* Wv   = (const float*)d_in[8];
    const float* bv   = (const float*)d_in[9];
    const float* nqw  = (const float*)d_in[10];
    const float* nkw  = (const float*)d_in[11];
    const float* Wo   = (const float*)d_in[12];
    const float* bo   = (const float*)d_in[13];
    float* out = (float*)d_out;

    float *px, *pq, *pk, *pv, *pa, *pwq, *pwk, *pwv, *pwo;
    cudaGetSymbolAddress((void**)&px, g_x);
    cudaGetSymbolAddress((void**)&pq, g_q);
    cudaGetSymbolAddress((void**)&pk, g_k);
    cudaGetSymbolAddress((void**)&pv, g_v);
    cudaGetSymbolAddress((void**)&pa, g_attn);
    cudaGetSymbolAddress((void**)&pwq, g_wq);
    cudaGetSymbolAddress((void**)&pwk, g_wk);
    cudaGetSymbolAddress((void**)&pwv, g_wv);
    cudaGetSymbolAddress((void**)&pwo, g_wo);
    __half *pqh, *pql, *pkh, *pkl;
    cudaGetSymbolAddress((void**)&pqh, g_qh);
    cudaGetSymbolAddress((void**)&pql, g_ql);
    cudaGetSymbolAddress((void**)&pkh, g_kh);
    cudaGetSymbolAddress((void**)&pkl, g_kl);

    cudaFuncSetAttribute(gemm_tf32, cudaFuncAttributeMaxDynamicSharedMemorySize, GEMM_SMEM);
    cudaFuncSetAttribute(attn_tc, cudaFuncAttributeMaxDynamicSharedMemorySize, ATTN_SMEM);

    concat_x<<<SEQ * DIM / 1024, 256>>>(hid, enc);

    const int nw4 = DIM * DIM / 1024;
    round_w<<<nw4, 256>>>(Wq, pwq);
    round_w<<<nw4, 256>>>(Wk, pwk);
    round_w<<<nw4, 256>>>(Wv, pwv);
    round_w<<<nw4, 256>>>(Wo, pwo);

    dim3 gqkv(DIM / 128, SEQ / 128);
    gemm_tf32<<<gqkv, 256, GEMM_SMEM>>>(px, pwq, bq, pq, SEQ, DIM, DIM);
    gemm_tf32<<<gqkv, 256, GEMM_SMEM>>>(px, pwk, bk, pk, SEQ, DIM, DIM);
    gemm_tf32<<<gqkv, 256, GEMM_SMEM>>>(px, pwv, bv, pv, SEQ, DIM, DIM);

    dim3 gn(SEQ, HEADS);
    norm_rope_split<<<gn, 128>>>(pq, nqw, rcos, rsin, pqh, pql, QSCALE);
    norm_rope_split<<<gn, 128>>>(pk, nkw, rcos, rsin, pkh, pkl, 1.0f);
    convert_vh<<<SEQ * DIM / 1024, 256>>>();

    dim3 ga(SEQ / 128, HEADS);
    attn_tc<<<ga, 256, ATTN_SMEM>>>();

    dim3 gout(DIM / 128, S_IMG / 128);
    gemm_tf32<<<gout, 256, GEMM_SMEM>>>(pa, pwo, bo, out, S_IMG, DIM, DIM);

    copy_txt<<<S_TXT * DIM / 1024, 256>>>(out);
}